// round 8
// baseline (speedup 1.0000x reference)
#include <cuda_runtime.h>
#include <cuda_bf16.h>
#include <math.h>
#include <stdint.h>

// ---------------- Problem constants ----------------
#define BATCH  2
#define SEQ    2048
#define DMODEL 1024
#define NHEAD  16
#define DK     64
#define MROWS  4096        // BATCH*SEQ
#define KDIM   1024
#define KC_COUNT 16        // KDIM / 64
#define STAGES 3

// Feature gate: tcgen05 exists only in the arch-specific target.
#if defined(__CUDA_ARCH_FEAT_SM103_ALL) || defined(__CUDA_ARCH_FEAT_SM100_ALL) || defined(__CUDA_ARCH_FEAT_SM101_ALL)
#define HAS_TC 1
#else
#define HAS_TC 0
#endif

// ---------------- Scratch (device globals; allocations forbidden) ----------
#define OFF_Q   0
#define OFF_K   4194304
#define OFF_V   8388608
#define OFF_CTX 12582912
#define OFF_WQ  16777216
#define OFF_WK  17825792
#define OFF_WV  18874368
#define OFF_WO  19922944
__device__ __nv_bfloat16 g_hi[20971520];
__device__ __nv_bfloat16 g_lo[20971520];

// Attention operand tiles (written by projection GEMM epilogues):
// Q,K: per (bh, stile) [128 seq x 64 dk] bf16 SW128 tiles (16KB each).
// V:   per (bh, stile) transposed [64 dk x 128 keys] blocked-atom SW128 tiles.
__device__ __align__(1024) __nv_bfloat16 g_tqh[4194304];
__device__ __align__(1024) __nv_bfloat16 g_tql[4194304];
__device__ __align__(1024) __nv_bfloat16 g_tkh[4194304];
__device__ __align__(1024) __nv_bfloat16 g_tkl[4194304];
__device__ __align__(1024) __nv_bfloat16 g_tvh[4194304];
__device__ __align__(1024) __nv_bfloat16 g_tvl[4194304];

// ---------------- PTX helpers ----------------
__device__ __forceinline__ uint32_t smem_u32(const void* p) {
    uint32_t a;
    asm("{ .reg .u64 t; cvta.to.shared.u64 t, %1; cvt.u32.u64 %0, t; }" : "=r"(a) : "l"(p));
    return a;
}

#define SWZ128(o) ((o) ^ (((o) >> 3) & 0x70))

#define MBARRIER_INIT(addr, cnt) \
    asm volatile("mbarrier.init.shared.b64 [%0], %1;" :: "r"(addr), "r"(cnt) : "memory")

#define MBARRIER_EXPECT_TX(addr, bytes) \
    asm volatile("mbarrier.arrive.expect_tx.shared.b64 _, [%0], %1;" :: "r"(addr), "r"(bytes) : "memory")

#define MBARRIER_WAIT_PARITY(addr, par) do {                                  \
    uint32_t _m = (addr); uint32_t _p = (par); uint32_t _d;                   \
    asm volatile("{\n\t.reg .pred p;\n\t"                                     \
        "mbarrier.try_wait.parity.acquire.cta.shared::cta.b64 p, [%1], %2;\n\t"\
        "selp.b32 %0, 1, 0, p;\n\t}" : "=r"(_d) : "r"(_m), "r"(_p) : "memory");\
    if (!_d) {                                                                \
        asm volatile("{\n\t.reg .pred P1;\n\t"                                \
        "W_%=:\n\t"                                                           \
        "mbarrier.try_wait.parity.acquire.cta.shared::cta.b64 P1, [%0], %1, 0x989680;\n\t" \
        "@P1 bra.uni D_%=;\n\t"                                               \
        "bra.uni W_%=;\n\t"                                                   \
        "D_%=:\n\t}" :: "r"(_m), "r"(_p) : "memory");                         \
    }                                                                         \
} while (0)

#define BULK_G2S(dst, src, bytes, mbar) \
    asm volatile("cp.async.bulk.shared::cluster.global.mbarrier::complete_tx::bytes [%0], [%1], %2, [%3];" \
        :: "r"(dst), "l"(src), "r"(bytes), "r"(mbar) : "memory")

#define TCGEN05_ALLOC(saddr, ncols) \
    asm volatile("tcgen05.alloc.cta_group::1.sync.aligned.shared::cta.b32 [%0], %1;" \
        :: "r"(saddr), "r"(ncols) : "memory")
#define TCGEN05_DEALLOC(tmem, ncols) \
    asm volatile("tcgen05.dealloc.cta_group::1.sync.aligned.b32 %0, %1;" :: "r"(tmem), "r"(ncols))
#define TCGEN05_RELINQ() \
    asm volatile("tcgen05.relinquish_alloc_permit.cta_group::1.sync.aligned;")
#define TCGEN05_COMMIT(mbar) \
    asm volatile("tcgen05.commit.cta_group::1.mbarrier::arrive::one.shared::cluster.b64 [%0];" \
        :: "r"(mbar) : "memory")
#define TCGEN05_FENCE_AFTER()  asm volatile("tcgen05.fence::after_thread_sync;" ::: "memory")
#define TCGEN05_FENCE_BEFORE() asm volatile("tcgen05.fence::before_thread_sync;" ::: "memory")
#define TCGEN05_WAIT_LD()      asm volatile("tcgen05.wait::ld.sync.aligned;" ::: "memory")
#define TCGEN05_WAIT_ST()      asm volatile("tcgen05.wait::st.sync.aligned;" ::: "memory")
#define FENCE_PROXY_ASYNC()    asm volatile("fence.proxy.async.shared::cta;" ::: "memory")

#define TCGEN05_LD_X32(r, taddr) \
    asm volatile("tcgen05.ld.sync.aligned.32x32b.x32.b32 " \
        "{%0, %1, %2, %3, %4, %5, %6, %7, %8, %9, %10, %11, %12, %13, %14, %15, " \
        " %16, %17, %18, %19, %20, %21, %22, %23, %24, %25, %26, %27, %28, %29, %30, %31}, [%32];" \
        : "=r"((r)[0]), "=r"((r)[1]), "=r"((r)[2]), "=r"((r)[3]), \
          "=r"((r)[4]), "=r"((r)[5]), "=r"((r)[6]), "=r"((r)[7]), \
          "=r"((r)[8]), "=r"((r)[9]), "=r"((r)[10]), "=r"((r)[11]), \
          "=r"((r)[12]), "=r"((r)[13]), "=r"((r)[14]), "=r"((r)[15]), \
          "=r"((r)[16]), "=r"((r)[17]), "=r"((r)[18]), "=r"((r)[19]), \
          "=r"((r)[20]), "=r"((r)[21]), "=r"((r)[22]), "=r"((r)[23]), \
          "=r"((r)[24]), "=r"((r)[25]), "=r"((r)[26]), "=r"((r)[27]), \
          "=r"((r)[28]), "=r"((r)[29]), "=r"((r)[30]), "=r"((r)[31]) \
        : "r"(taddr))

#define TCGEN05_ST_X16(taddr, r) \
    asm volatile("tcgen05.st.sync.aligned.32x32b.x16.b32 [%0], " \
        "{%1, %2, %3, %4, %5, %6, %7, %8, %9, %10, %11, %12, %13, %14, %15, %16};" \
        :: "r"(taddr), \
           "r"((r)[0]), "r"((r)[1]), "r"((r)[2]), "r"((r)[3]), \
           "r"((r)[4]), "r"((r)[5]), "r"((r)[6]), "r"((r)[7]), \
           "r"((r)[8]), "r"((r)[9]), "r"((r)[10]), "r"((r)[11]), \
           "r"((r)[12]), "r"((r)[13]), "r"((r)[14]), "r"((r)[15]) \
        : "memory")

// SMEM descriptor: SW128, version=1, SBO=64, LBO=1 (K-major bf16, 128B rows)
#define SMEM_DESC_BASE ((uint64_t(2) << 61) | (uint64_t(1) << 46) | (uint64_t(64) << 32) | (uint64_t(1) << 16))
#define MAKE_DESC(a) (SMEM_DESC_BASE | ((uint64_t)((a) >> 4) & 0x3FFF))

#define IDESC_N128 0x08200490u   // M=128, N=128
#define IDESC_N64  0x08100490u   // M=128, N=64

__device__ __forceinline__ void mma_ss(uint32_t d_tmem, uint64_t a_desc, uint64_t b_desc,
                                       uint32_t idesc, bool acc) {
#if HAS_TC
    uint32_t en = acc ? 1u : 0u;
    asm volatile(
        "{\n\t.reg .pred p;\n\t"
        "setp.ne.u32 p, %4, 0;\n\t"
        "tcgen05.mma.cta_group::1.kind::f16 [%0], %1, %2, %3, p;\n\t}"
        :: "r"(d_tmem), "l"(a_desc), "l"(b_desc), "r"(idesc), "r"(en) : "memory");
#endif
}
__device__ __forceinline__ void mma_ts(uint32_t d_tmem, uint32_t a_tmem, uint64_t b_desc,
                                       uint32_t idesc, bool acc) {
#if HAS_TC
    uint32_t en = acc ? 1u : 0u;
    asm volatile(
        "{\n\t.reg .pred p;\n\t"
        "setp.ne.u32 p, %4, 0;\n\t"
        "tcgen05.mma.cta_group::1.kind::f16 [%0], [%1], %2, %3, p;\n\t}"
        :: "r"(d_tmem), "r"(a_tmem), "l"(b_desc), "r"(idesc), "r"(en) : "memory");
#endif
}

__device__ __forceinline__ float ex2f(float x) {
    float y;
    asm("ex2.approx.f32 %0, %1;" : "=f"(y) : "f"(x));
    return y;
}
__device__ __forceinline__ uint32_t pack_bf16x2(float a, float b) {
    __nv_bfloat16 h0 = __float2bfloat16(a), h1 = __float2bfloat16(b);
    return ((uint32_t)__bfloat16_as_ushort(h1) << 16) | (uint32_t)__bfloat16_as_ushort(h0);
}
__device__ __forceinline__ void split2(float x, float y, uint32_t& h, uint32_t& l) {
    __nv_bfloat16 hx = __float2bfloat16(x), hy = __float2bfloat16(y);
    h = ((uint32_t)__bfloat16_as_ushort(hy) << 16) | (uint32_t)__bfloat16_as_ushort(hx);
    l = pack_bf16x2(x - __bfloat162float(hx), y - __bfloat162float(hy));
}

// ---------------- Converter: 8 elems/thread, 16B coalesced stores -----------
__device__ __forceinline__ void convert_body8(const float* __restrict__ src,
                                              __nv_bfloat16* __restrict__ hi,
                                              __nv_bfloat16* __restrict__ lo, int mtiles) {
#if HAS_TC
    int idx = blockIdx.x * 256 + threadIdx.x;   // chunk index: m*128 + ck
    int m  = idx >> 7;
    int ck = idx & 127;
    int kc = ck >> 3;
    int r  = m & 127, mt = m >> 7;
    uint32_t off = SWZ128((uint32_t)(r * 128 + (ck & 7) * 16));
    size_t base = ((size_t)(kc * mtiles + mt) << 14) + off;

    const float4* s4 = reinterpret_cast<const float4*>(src + (size_t)m * KDIM + ck * 8);
    float4 a = s4[0], b = s4[1];
    uint4 hq, lq;
    split2(a.x, a.y, hq.x, lq.x);
    split2(a.z, a.w, hq.y, lq.y);
    split2(b.x, b.y, hq.z, lq.z);
    split2(b.z, b.w, hq.w, lq.w);
    *reinterpret_cast<uint4*>(reinterpret_cast<char*>(hi) + base) = hq;
    *reinterpret_cast<uint4*>(reinterpret_cast<char*>(lo) + base) = lq;
#endif
}

__global__ void __launch_bounds__(256)
convert_acts(const float* __restrict__ q, const float* __restrict__ k,
             const float* __restrict__ v) {
#if HAS_TC
    const float* src = (blockIdx.z == 0) ? q : (blockIdx.z == 1) ? k : v;
    size_t off = (blockIdx.z == 0) ? OFF_Q : (blockIdx.z == 1) ? OFF_K : OFF_V;
    convert_body8(src, g_hi + off, g_lo + off, 32);
#endif
}

__global__ void __launch_bounds__(256)
convert_wts(const float* __restrict__ wq, const float* __restrict__ wk,
            const float* __restrict__ wv, const float* __restrict__ wo) {
#if HAS_TC
    const float* src = (blockIdx.z == 0) ? wq : (blockIdx.z == 1) ? wk :
                       (blockIdx.z == 2) ? wv : wo;
    size_t off = (blockIdx.z == 0) ? OFF_WQ : (blockIdx.z == 1) ? OFF_WK :
                 (blockIdx.z == 2) ? OFF_WV : OFF_WO;
    convert_body8(src, g_hi + off, g_lo + off, 8);
#endif
}

// ---------------- tcgen05 split-bf16 GEMM (unchanged, proven) ---------------
#define TILE_B   16384
#define STAGE_B  (4 * TILE_B)
#define SM_CTRL  0
#define SM_FULL(s)  (16 + (s) * 8)
#define SM_EMPTY(s) (48 + (s) * 8)
#define SM_DONE  80
#define SM_TILES 1024
#define SM_A_HI(s) (SM_TILES + (s) * STAGE_B)
#define SM_A_LO(s) (SM_A_HI(s) + TILE_B)
#define SM_B_HI(s) (SM_A_LO(s) + TILE_B)
#define SM_B_LO(s) (SM_B_HI(s) + TILE_B)
#define GEMM_SMEM (SM_TILES + STAGES * STAGE_B)   // 197632

__global__ void __launch_bounds__(256)
gemm_bf16s(const __nv_bfloat16* __restrict__ ahi, const __nv_bfloat16* __restrict__ alo,
           const __nv_bfloat16* __restrict__ bhi, const __nv_bfloat16* __restrict__ blo,
           float* __restrict__ outflat, int dst, int mtilesA) {
#if HAS_TC
    extern __shared__ char smem[];
    const uint32_t sb = smem_u32(smem);
    const int tid = threadIdx.x, wid = tid >> 5, lid = tid & 31;
    const int mt = blockIdx.y, nt = blockIdx.x;

    if (tid == 0) {
        #pragma unroll
        for (int s = 0; s < STAGES; s++) {
            MBARRIER_INIT(sb + SM_FULL(s), 1);
            MBARRIER_INIT(sb + SM_EMPTY(s), 1);
        }
        MBARRIER_INIT(sb + SM_DONE, 1);
        FENCE_PROXY_ASYNC();
    }
    if (wid == 0) TCGEN05_ALLOC(sb + SM_CTRL, 128);
    __syncthreads();

    uint32_t tmem;
    asm volatile("ld.shared.b32 %0, [%1];" : "=r"(tmem) : "r"(sb + SM_CTRL));

    if (tid == 32) {
        int ph[STAGES] = {1, 1, 1};
        for (int kc = 0; kc < KC_COUNT; kc++) {
            int s = kc % STAGES;
            MBARRIER_WAIT_PARITY(sb + SM_EMPTY(s), ph[s]); ph[s] ^= 1;
            MBARRIER_EXPECT_TX(sb + SM_FULL(s), 4 * TILE_B);
            const char* at = (const char*)ahi + ((size_t)(kc * mtilesA + mt) << 14);
            const char* al = (const char*)alo + ((size_t)(kc * mtilesA + mt) << 14);
            const char* bt = (const char*)bhi + ((size_t)(kc * 8 + nt) << 14);
            const char* bl = (const char*)blo + ((size_t)(kc * 8 + nt) << 14);
            BULK_G2S(sb + SM_A_HI(s), at, TILE_B, sb + SM_FULL(s));
            BULK_G2S(sb + SM_A_LO(s), al, TILE_B, sb + SM_FULL(s));
            BULK_G2S(sb + SM_B_HI(s), bt, TILE_B, sb + SM_FULL(s));
            BULK_G2S(sb + SM_B_LO(s), bl, TILE_B, sb + SM_FULL(s));
        }
    } else if (tid == 0) {
        int ph[STAGES] = {0, 0, 0};
        bool first = true;
        for (int kc = 0; kc < KC_COUNT; kc++) {
            int s = kc % STAGES;
            MBARRIER_WAIT_PARITY(sb + SM_FULL(s), ph[s]); ph[s] ^= 1;
            uint64_t dah = MAKE_DESC(sb + SM_A_HI(s));
            uint64_t dal = MAKE_DESC(sb + SM_A_LO(s));
            uint64_t dbh = MAKE_DESC(sb + SM_B_HI(s));
            uint64_t dbl = MAKE_DESC(sb + SM_B_LO(s));
            #pragma unroll
            for (int ks = 0; ks < 4; ks++) {
                mma_ss(tmem, dah + ks * 2, dbh + ks * 2, IDESC_N128, !first); first = false;
                mma_ss(tmem, dah + ks * 2, dbl + ks * 2, IDESC_N128, true);
                mma_ss(tmem, dal + ks * 2, dbh + ks * 2, IDESC_N128, true);
            }
            TCGEN05_COMMIT(sb + SM_EMPTY(s));
        }
        TCGEN05_COMMIT(sb + SM_DONE);
    }

    MBARRIER_WAIT_PARITY(sb + SM_DONE, 0);
    TCGEN05_FENCE_AFTER();

    uint32_t d[64];
    const int colbase = (wid >> 2) * 64;
    TCGEN05_LD_X32(d, tmem + colbase);
    TCGEN05_LD_X32(d + 32, tmem + colbase + 32);
    TCGEN05_WAIT_LD();
    TCGEN05_FENCE_BEFORE();

    const int m = mt * 128 + (wid & 3) * 32 + lid;
    const int ng = nt * 128 + colbase;

    if (dst < 3) {
        const int b = m >> 11, sq = m & (SEQ - 1);
        const int h = ng >> 6;
        const int tile = (b * NHEAD + h) * 16 + (sq >> 7);
        const int rr = sq & 127;
        if (dst == 0 || dst == 1) {
            char* hb = (char*)(dst == 0 ? g_tqh : g_tkh) + ((size_t)tile << 14);
            char* lb = (char*)(dst == 0 ? g_tql : g_tkl) + ((size_t)tile << 14);
            #pragma unroll
            for (int c = 0; c < 64; c += 8) {
                uint4 hq, lq;
                split2(__uint_as_float(d[c + 0]), __uint_as_float(d[c + 1]), hq.x, lq.x);
                split2(__uint_as_float(d[c + 2]), __uint_as_float(d[c + 3]), hq.y, lq.y);
                split2(__uint_as_float(d[c + 4]), __uint_as_float(d[c + 5]), hq.z, lq.z);
                split2(__uint_as_float(d[c + 6]), __uint_as_float(d[c + 7]), hq.w, lq.w);
                uint32_t off = SWZ128((uint32_t)(rr * 128 + c * 2));
                *(uint4*)(hb + off) = hq;
                *(uint4*)(lb + off) = lq;
            }
        } else {
            char* hb = (char*)g_tvh + ((size_t)tile << 14);
            char* lb = (char*)g_tvl + ((size_t)tile << 14);
            const int kin = rr;
            #pragma unroll
            for (int c = 0; c < 64; c++) {
                float v0 = __uint_as_float(d[c]);
                __nv_bfloat16 h0 = __float2bfloat16(v0);
                __nv_bfloat16 l0 = __float2bfloat16(v0 - __bfloat162float(h0));
                uint32_t bo = (uint32_t)(((c >> 3) + (kin >> 6) * 8) * 1024 +
                                         (c & 7) * 128 + (kin & 63) * 2);
                uint32_t off = SWZ128(bo);
                *(__nv_bfloat16*)(hb + off) = h0;
                *(__nv_bfloat16*)(lb + off) = l0;
            }
        }
    } else {
        float* row = outflat + (size_t)m * DMODEL + ng;
        #pragma unroll
        for (int c = 0; c < 64; c += 4) {
            float4 v = make_float4(__uint_as_float(d[c]), __uint_as_float(d[c + 1]),
                                   __uint_as_float(d[c + 2]), __uint_as_float(d[c + 3]));
            *reinterpret_cast<float4*>(row + c) = v;
        }
    }

    __syncthreads();
    if (wid == 0) {
        TCGEN05_RELINQ();
        TCGEN05_DEALLOC(tmem, 128);
    }
#endif
}

// ---------------- tcgen05 flash attention v4: 256 query rows per CTA --------
// Grid (8, 16, 2) = 256 CTAs (1.73 waves). Two M-tiles per CTA share each
// K/V stage. TMEM: S0@0(128), S1@128(128), O0@256(64), O1@320(64),
// PH@384(64), PL@448(64) = 512. P region shared between tiles (serialized by
// OD waits). 2-stage TMA ring; refill gated on OD1(j-1).
#define F_TM     0
#define F_FULL(u) (16 + (u) * 8)
#define F_SD(t)   (32 + (t) * 8)
#define F_OD(t)   (48 + (t) * 8)
#define F_QFULL  64
#define F_LRED0  512
#define F_LRED1  1536
#define F_Q      4096               // Qh0,Ql0,Qh1,Ql1 (4 x 16KB)
#define F_STG    (F_Q + 65536)      // 69632
#define F_STGSZ  65536
#define FLASH_SMEM (F_STG + 2 * F_STGSZ)   // 200704
#define TC_S0  0
#define TC_S1  128
#define TC_O0  256
#define TC_O1  320
#define TC_PH  384
#define TC_PL  448

__global__ void __launch_bounds__(256)
flash_tc(const int* __restrict__ mask) {
#if HAS_TC
    extern __shared__ char fsm[];
    const uint32_t sb = smem_u32(fsm);
    const int tid = threadIdx.x;
    const int lane = tid & 31;
    const int sp = (tid >> 5) & 3;
    const int ch = tid >> 7;              // column half
    const int r = sp * 32 + lane;         // row 0..127 within a tile
    const int bh = blockIdx.z * NHEAD + blockIdx.y;
    const int qt = blockIdx.x;            // 0..7 (256-row blocks)

    if (tid == 0) {
        MBARRIER_INIT(sb + F_FULL(0), 1);
        MBARRIER_INIT(sb + F_FULL(1), 1);
        MBARRIER_INIT(sb + F_SD(0), 1);
        MBARRIER_INIT(sb + F_SD(1), 1);
        MBARRIER_INIT(sb + F_OD(0), 1);
        MBARRIER_INIT(sb + F_OD(1), 1);
        MBARRIER_INIT(sb + F_QFULL, 1);
        FENCE_PROXY_ASYNC();
    }
    if ((tid >> 5) == 0) TCGEN05_ALLOC(sb + F_TM, 512);
    __syncthreads();

    uint32_t tmem;
    asm volatile("ld.shared.b32 %0, [%1];" : "=r"(tmem) : "r"(sb + F_TM));

    auto issue_stage = [&](int tile, int u) {
        const size_t koff = ((size_t)(bh * 16 + tile)) << 14;
        const uint32_t d1 = sb + F_STG + u * F_STGSZ;
        MBARRIER_EXPECT_TX(sb + F_FULL(u), 4 * TILE_B);
        BULK_G2S(d1 + 0,     (const char*)g_tkh + koff, TILE_B, sb + F_FULL(u));
        BULK_G2S(d1 + 16384, (const char*)g_tkl + koff, TILE_B, sb + F_FULL(u));
        BULK_G2S(d1 + 32768, (const char*)g_tvh + koff, TILE_B, sb + F_FULL(u));
        BULK_G2S(d1 + 49152, (const char*)g_tvl + koff, TILE_B, sb + F_FULL(u));
    };
    auto do_mma1 = [&](int t, uint32_t stg) {   // S_t = Q_t @ K^T (3-term)
        const uint64_t dqh = MAKE_DESC(sb + F_Q + t * 32768);
        const uint64_t dql = MAKE_DESC(sb + F_Q + t * 32768 + 16384);
        const uint64_t dkh = MAKE_DESC(stg);
        const uint64_t dkl = MAKE_DESC(stg + 16384);
        const uint32_t sdst = tmem + (t ? TC_S1 : TC_S0);
        #pragma unroll
        for (int ks = 0; ks < 4; ks++)
            mma_ss(sdst, dqh + ks * 2, dkh + ks * 2, IDESC_N128, ks > 0);
        #pragma unroll
        for (int ks = 0; ks < 4; ks++)
            mma_ss(sdst, dqh + ks * 2, dkl + ks * 2, IDESC_N128, true);
        #pragma unroll
        for (int ks = 0; ks < 4; ks++)
            mma_ss(sdst, dql + ks * 2, dkh + ks * 2, IDESC_N128, true);
    };
    auto do_mma2 = [&](int t, uint32_t stg, bool first) {   // O_t += P @ V^T
        const uint64_t dvh = MAKE_DESC(stg + 32768);
        const uint64_t dvl = MAKE_DESC(stg + 49152);
        const uint32_t odst = tmem + (t ? TC_O1 : TC_O0);
        const int voff[8] = {0, 2, 4, 6, 512, 514, 516, 518};
        #pragma unroll
        for (int ks = 0; ks < 8; ks++)
            mma_ts(odst, tmem + TC_PH + ks * 8, dvh + voff[ks], IDESC_N64,
                   !(first && ks == 0));
        #pragma unroll
        for (int ks = 0; ks < 8; ks++)
            mma_ts(odst, tmem + TC_PH + ks * 8, dvl + voff[ks], IDESC_N64, true);
        #pragma unroll
        for (int ks = 0; ks < 8; ks++)
            mma_ts(odst, tmem + TC_PL + ks * 8, dvh + voff[ks], IDESC_N64, true);
    };

    // Preamble: Q tiles (2 m-tiles, hi+lo) + stages 0,1 <- key tiles 0,1.
    if (tid == 0) {
        MBARRIER_EXPECT_TX(sb + F_QFULL, 65536);
        #pragma unroll
        for (int t = 0; t < 2; t++) {
            const size_t qoff = ((size_t)(bh * 16 + qt * 2 + t)) << 14;
            BULK_G2S(sb + F_Q + t * 32768,         (const char*)g_tqh + qoff, TILE_B, sb + F_QFULL);
            BULK_G2S(sb + F_Q + t * 32768 + 16384, (const char*)g_tql + qoff, TILE_B, sb + F_QFULL);
        }
        issue_stage(0, 0);
        issue_stage(1, 1);
        MBARRIER_WAIT_PARITY(sb + F_QFULL, 0);
    }

    const float cs = 0.125f * 1.4426950408889634f;
    const float CB = 20.0f;
    const int* mk = mask + blockIdx.z * SEQ;
    float lsum0 = 0.f, lsum1 = 0.f;

    for (int j = 0; j < 16; j++) {
        const int s = j & 1;
        const uint32_t stg = sb + F_STG + s * F_STGSZ;

        if (tid == 0) {
            // Refill stage s (holds consumed tile j-2... wait: stage (j+1)&1
            // holds tile j+1 still loading/loaded; stage s=j&1 holds tile j).
            // Refill of tile j+1 happened at top of iter j-1 into stage (j+1)&1.
            // Here: refill stage s_prev=(j+1)&1 is WRONG; we refill the stage
            // consumed two iters ago: at top of iter j (j>=1), stage (j+1)&1
            // currently holds tile j+1 (ok), and we refill nothing yet; the
            // stage to refill is s=j&1 AFTER this iter. Instead: refill tile
            // j+1's successor at the right time: at top of iter j (j>=1),
            // stage (j+1)&1 was consumed at iter j-1 (tile j-1) and must get
            // tile j+1 -- gated on OD1(j-1).
            if (j >= 1 && j + 1 <= 15) {
                MBARRIER_WAIT_PARITY(sb + F_OD(1), (j - 1) & 1);
                issue_stage(j + 1, (j + 1) & 1);
            }
            // MMA1s for this iter: stage s holds tile j (fill #(j/2)).
            MBARRIER_WAIT_PARITY(sb + F_FULL(s), (j >> 1) & 1);
            do_mma1(0, stg);
            TCGEN05_COMMIT(sb + F_SD(0));
            do_mma1(1, stg);
            TCGEN05_COMMIT(sb + F_SD(1));
        }

        #pragma unroll
        for (int t = 0; t < 2; t++) {
            MBARRIER_WAIT_PARITY(sb + F_SD(t), j & 1);
            TCGEN05_FENCE_AFTER();
            const uint32_t sbase = tmem + (t ? TC_S1 : TC_S0) + ch * 64;
            const int* mrow = mk + j * 128 + ch * 64;
            float lacc = 0.f;

            #pragma unroll
            for (int half = 0; half < 2; half++) {
                uint32_t sr[32];
                TCGEN05_LD_X32(sr, sbase + half * 32);
                TCGEN05_WAIT_LD();

                uint32_t ph[16], pl[16];
                const int* m2 = mrow + half * 32;
                #pragma unroll
                for (int g = 0; g < 8; g++) {
                    int4 mm = *reinterpret_cast<const int4*>(m2 + 4 * g);
                    float p0 = mm.x ? ex2f(fmaf(__uint_as_float(sr[4 * g + 0]), cs, -CB)) : 0.f;
                    float p1 = mm.y ? ex2f(fmaf(__uint_as_float(sr[4 * g + 1]), cs, -CB)) : 0.f;
                    float p2 = mm.z ? ex2f(fmaf(__uint_as_float(sr[4 * g + 2]), cs, -CB)) : 0.f;
                    float p3 = mm.w ? ex2f(fmaf(__uint_as_float(sr[4 * g + 3]), cs, -CB)) : 0.f;
                    lacc += (p0 + p1) + (p2 + p3);
                    split2(p0, p1, ph[2 * g],     pl[2 * g]);
                    split2(p2, p3, ph[2 * g + 1], pl[2 * g + 1]);
                }

                // P region is shared: before the FIRST store of each tile,
                // the previous MMA2 reading P must be complete.
                if (half == 0) {
                    if (t == 0) {
                        if (j >= 1) {   // MMA2(t1, j-1)
                            MBARRIER_WAIT_PARITY(sb + F_OD(1), (j - 1) & 1);
                            TCGEN05_FENCE_AFTER();
                        }
                    } else {            // MMA2(t0, j) committed this iter
                        MBARRIER_WAIT_PARITY(sb + F_OD(0), j & 1);
                        TCGEN05_FENCE_AFTER();
                    }
                }
                TCGEN05_ST_X16(tmem + TC_PH + ch * 32 + half * 16, ph);
                TCGEN05_ST_X16(tmem + TC_PL + ch * 32 + half * 16, pl);
            }
            if (t == 0) lsum0 += lacc; else lsum1 += lacc;

            TCGEN05_WAIT_ST();
            TCGEN05_FENCE_BEFORE();
            __syncthreads();

            if (tid == 0) {
                TCGEN05_FENCE_AFTER();
                do_mma2(t, stg, j == 0);
                TCGEN05_COMMIT(sb + F_OD(t));
            }
        }
    }

    // Epilogue: final MMA2(t1,15) -> OD(1) 16th flip -> wait parity 15&1 = 1.
    MBARRIER_WAIT_PARITY(sb + F_OD(1), 1);
    TCGEN05_FENCE_AFTER();

    float* lred0 = (float*)(fsm + F_LRED0);
    float* lred1 = (float*)(fsm + F_LRED1);
    lred0[ch * 128 + r] = lsum0;
    lred1[ch * 128 + r] = lsum1;
    __syncthreads();
    const float inv0 = 1.f / (lsum0 + lred0[(1 - ch) * 128 + r]);
    const float inv1 = 1.f / (lsum1 + lred1[(1 - ch) * 128 + r]);

    const int h = blockIdx.y;
    #pragma unroll
    for (int t = 0; t < 2; t++) {
        uint32_t od[32];
        TCGEN05_LD_X32(od, tmem + (t ? TC_O1 : TC_O0) + ch * 32);
        TCGEN05_WAIT_LD();
        const float inv = t ? inv1 : inv0;
        const int mt_g = blockIdx.z * 16 + qt * 2 + t;
        char* hb = (char*)g_hi + (((size_t)OFF_CTX) << 1) + (((size_t)(h * 32 + mt_g)) << 14);
        char* lb = (char*)g_lo + (((size_t)OFF_CTX) << 1) + (((size_t)(h * 32 + mt_g)) << 14);
        #pragma unroll
        for (int c = 0; c < 32; c += 8) {
            uint4 hq, lq;
            split2(__uint_as_float(od[c + 0]) * inv, __uint_as_float(od[c + 1]) * inv, hq.x, lq.x);
            split2(__uint_as_float(od[c + 2]) * inv, __uint_as_float(od[c + 3]) * inv, hq.y, lq.y);
            split2(__uint_as_float(od[c + 4]) * inv, __uint_as_float(od[c + 5]) * inv, hq.z, lq.z);
            split2(__uint_as_float(od[c + 6]) * inv, __uint_as_float(od[c + 7]) * inv, hq.w, lq.w);
            uint32_t off = SWZ128((uint32_t)(r * 128 + (ch * 32 + c) * 2));
            *(uint4*)(hb + off) = hq;
            *(uint4*)(lb + off) = lq;
        }
    }
    TCGEN05_FENCE_BEFORE();

    __syncthreads();
    if ((tid >> 5) == 0) {
        TCGEN05_RELINQ();
        TCGEN05_DEALLOC(tmem, 512);
    }
#endif
}

// ---------------- Launch -----------------------------------------------------
extern "C" void kernel_launch(void* const* d_in, const int* in_sizes, int n_in,
                              void* d_out, int out_size) {
    const float* q    = (const float*)d_in[0];
    const float* k    = (const float*)d_in[1];
    const float* v    = (const float*)d_in[2];
    const int*   mask = (const int*)  d_in[3];
    const float* Wq   = (const float*)d_in[4];
    const float* Wk   = (const float*)d_in[5];
    const float* Wv   = (const float*)d_in[6];
    const float* Wo   = (const float*)d_in[7];
    float* out = (float*)d_out;

    __nv_bfloat16 *hi_ptr = nullptr, *lo_ptr = nullptr;
    cudaGetSymbolAddress((void**)&hi_ptr, g_hi);
    cudaGetSymbolAddress((void**)&lo_ptr, g_lo);

    cudaFuncSetAttribute(gemm_bf16s, cudaFuncAttributeMaxDynamicSharedMemorySize, GEMM_SMEM);
    cudaFuncSetAttribute(flash_tc, cudaFuncAttributeMaxDynamicSharedMemorySize, FLASH_SMEM);

    dim3 ggrid(8, 32);
    dim3 fa_grid_tc(8, NHEAD, BATCH);   // 256 CTAs, 256 rows each

    convert_acts<<<dim3(2048, 1, 3), 256>>>(q, k, v);
    convert_wts<<<dim3(512, 1, 4), 256>>>(Wq, Wk, Wv, Wo);

    gemm_bf16s<<<ggrid, 256, GEMM_SMEM>>>(hi_ptr + OFF_Q, lo_ptr + OFF_Q,
                                          hi_ptr + OFF_WQ, lo_ptr + OFF_WQ, nullptr, 0, 32);
    gemm_bf16s<<<ggrid, 256, GEMM_SMEM>>>(hi_ptr + OFF_K, lo_ptr + OFF_K,
                                          hi_ptr + OFF_WK, lo_ptr + OFF_WK, nullptr, 1, 32);
    gemm_bf16s<<<ggrid, 256, GEMM_SMEM>>>(hi_ptr + OFF_V, lo_ptr + OFF_V,
                                          hi_ptr + OFF_WV, lo_ptr + OFF_WV, nullptr, 2, 32);

    flash_tc<<<fa_grid_tc, 256, FLASH_SMEM>>>(mask);

    gemm_bf16s<<<ggrid, 256, GEMM_SMEM>>>(hi_ptr + OFF_CTX, lo_ptr + OFF_CTX,
                                          hi_ptr + OFF_WO, lo_ptr + OFF_WO, out, 3, 32);
}

// round 9
// speedup vs baseline: 1.1464x; 1.1464x over previous
#include <cuda_runtime.h>
#include <cuda_bf16.h>
#include <math.h>
#include <stdint.h>

// ---------------- Problem constants ----------------
#define BATCH  2
#define SEQ    2048
#define DMODEL 1024
#define NHEAD  16
#define DK     64
#define MROWS  4096        // BATCH*SEQ
#define KDIM   1024
#define KC_COUNT 16        // KDIM / 64

// Feature gate: tcgen05 exists only in the arch-specific target.
#if defined(__CUDA_ARCH_FEAT_SM103_ALL) || defined(__CUDA_ARCH_FEAT_SM100_ALL) || defined(__CUDA_ARCH_FEAT_SM101_ALL)
#define HAS_TC 1
#else
#define HAS_TC 0
#endif

// ---------------- Scratch (device globals; allocations forbidden) ----------
#define OFF_Q   0
#define OFF_K   4194304
#define OFF_V   8388608
#define OFF_CTX 12582912
#define OFF_WQ  16777216
#define OFF_WK  17825792
#define OFF_WV  18874368
#define OFF_WO  19922944
__device__ __nv_bfloat16 g_hi[20971520];
__device__ __nv_bfloat16 g_lo[20971520];

// Attention operand tiles (written by projection GEMM epilogues):
// Q,K: per (bh, stile) [128 seq x 64 dk] bf16 SW128 tiles (16KB each).
// V:   per (bh, stile) transposed [64 dk x 128 keys] blocked-atom SW128 tiles.
__device__ __align__(1024) __nv_bfloat16 g_tqh[4194304];
__device__ __align__(1024) __nv_bfloat16 g_tql[4194304];
__device__ __align__(1024) __nv_bfloat16 g_tkh[4194304];
__device__ __align__(1024) __nv_bfloat16 g_tkl[4194304];
__device__ __align__(1024) __nv_bfloat16 g_tvh[4194304];
__device__ __align__(1024) __nv_bfloat16 g_tvl[4194304];

// ---------------- PTX helpers ----------------
__device__ __forceinline__ uint32_t smem_u32(const void* p) {
    uint32_t a;
    asm("{ .reg .u64 t; cvta.to.shared.u64 t, %1; cvt.u32.u64 %0, t; }" : "=r"(a) : "l"(p));
    return a;
}

#define SWZ128(o) ((o) ^ (((o) >> 3) & 0x70))

#define MBARRIER_INIT(addr, cnt) \
    asm volatile("mbarrier.init.shared.b64 [%0], %1;" :: "r"(addr), "r"(cnt) : "memory")

#define MBARRIER_EXPECT_TX(addr, bytes) \
    asm volatile("mbarrier.arrive.expect_tx.shared.b64 _, [%0], %1;" :: "r"(addr), "r"(bytes) : "memory")

#define MBARRIER_WAIT_PARITY(addr, par) do {                                  \
    uint32_t _m = (addr); uint32_t _p = (par); uint32_t _d;                   \
    asm volatile("{\n\t.reg .pred p;\n\t"                                     \
        "mbarrier.try_wait.parity.acquire.cta.shared::cta.b64 p, [%1], %2;\n\t"\
        "selp.b32 %0, 1, 0, p;\n\t}" : "=r"(_d) : "r"(_m), "r"(_p) : "memory");\
    if (!_d) {                                                                \
        asm volatile("{\n\t.reg .pred P1;\n\t"                                \
        "W_%=:\n\t"                                                           \
        "mbarrier.try_wait.parity.acquire.cta.shared::cta.b64 P1, [%0], %1, 0x989680;\n\t" \
        "@P1 bra.uni D_%=;\n\t"                                               \
        "bra.uni W_%=;\n\t"                                                   \
        "D_%=:\n\t}" :: "r"(_m), "r"(_p) : "memory");                         \
    }                                                                         \
} while (0)

#define BULK_G2S(dst, src, bytes, mbar) \
    asm volatile("cp.async.bulk.shared::cluster.global.mbarrier::complete_tx::bytes [%0], [%1], %2, [%3];" \
        :: "r"(dst), "l"(src), "r"(bytes), "r"(mbar) : "memory")

#define TCGEN05_ALLOC(saddr, ncols) \
    asm volatile("tcgen05.alloc.cta_group::1.sync.aligned.shared::cta.b32 [%0], %1;" \
        :: "r"(saddr), "r"(ncols) : "memory")
#define TCGEN05_DEALLOC(tmem, ncols) \
    asm volatile("tcgen05.dealloc.cta_group::1.sync.aligned.b32 %0, %1;" :: "r"(tmem), "r"(ncols))
#define TCGEN05_RELINQ() \
    asm volatile("tcgen05.relinquish_alloc_permit.cta_group::1.sync.aligned;")
#define TCGEN05_COMMIT(mbar) \
    asm volatile("tcgen05.commit.cta_group::1.mbarrier::arrive::one.shared::cluster.b64 [%0];" \
        :: "r"(mbar) : "memory")
#define TCGEN05_FENCE_AFTER()  asm volatile("tcgen05.fence::after_thread_sync;" ::: "memory")
#define TCGEN05_FENCE_BEFORE() asm volatile("tcgen05.fence::before_thread_sync;" ::: "memory")
#define TCGEN05_WAIT_LD()      asm volatile("tcgen05.wait::ld.sync.aligned;" ::: "memory")
#define TCGEN05_WAIT_ST()      asm volatile("tcgen05.wait::st.sync.aligned;" ::: "memory")
#define FENCE_PROXY_ASYNC()    asm volatile("fence.proxy.async.shared::cta;" ::: "memory")

#define TCGEN05_LD_X32(r, taddr) \
    asm volatile("tcgen05.ld.sync.aligned.32x32b.x32.b32 " \
        "{%0, %1, %2, %3, %4, %5, %6, %7, %8, %9, %10, %11, %12, %13, %14, %15, " \
        " %16, %17, %18, %19, %20, %21, %22, %23, %24, %25, %26, %27, %28, %29, %30, %31}, [%32];" \
        : "=r"((r)[0]), "=r"((r)[1]), "=r"((r)[2]), "=r"((r)[3]), \
          "=r"((r)[4]), "=r"((r)[5]), "=r"((r)[6]), "=r"((r)[7]), \
          "=r"((r)[8]), "=r"((r)[9]), "=r"((r)[10]), "=r"((r)[11]), \
          "=r"((r)[12]), "=r"((r)[13]), "=r"((r)[14]), "=r"((r)[15]), \
          "=r"((r)[16]), "=r"((r)[17]), "=r"((r)[18]), "=r"((r)[19]), \
          "=r"((r)[20]), "=r"((r)[21]), "=r"((r)[22]), "=r"((r)[23]), \
          "=r"((r)[24]), "=r"((r)[25]), "=r"((r)[26]), "=r"((r)[27]), \
          "=r"((r)[28]), "=r"((r)[29]), "=r"((r)[30]), "=r"((r)[31]) \
        : "r"(taddr))

#define TCGEN05_ST_X16(taddr, r) \
    asm volatile("tcgen05.st.sync.aligned.32x32b.x16.b32 [%0], " \
        "{%1, %2, %3, %4, %5, %6, %7, %8, %9, %10, %11, %12, %13, %14, %15, %16};" \
        :: "r"(taddr), \
           "r"((r)[0]), "r"((r)[1]), "r"((r)[2]), "r"((r)[3]), \
           "r"((r)[4]), "r"((r)[5]), "r"((r)[6]), "r"((r)[7]), \
           "r"((r)[8]), "r"((r)[9]), "r"((r)[10]), "r"((r)[11]), \
           "r"((r)[12]), "r"((r)[13]), "r"((r)[14]), "r"((r)[15]) \
        : "memory")

// SMEM descriptor: SW128, version=1, SBO=64, LBO=1 (K-major bf16, 128B rows)
#define SMEM_DESC_BASE ((uint64_t(2) << 61) | (uint64_t(1) << 46) | (uint64_t(64) << 32) | (uint64_t(1) << 16))
#define MAKE_DESC(a) (SMEM_DESC_BASE | ((uint64_t)((a) >> 4) & 0x3FFF))

#define IDESC_N128 0x08200490u   // M=128, N=128
#define IDESC_N64  0x08100490u   // M=128, N=64

__device__ __forceinline__ void mma_ss(uint32_t d_tmem, uint64_t a_desc, uint64_t b_desc,
                                       uint32_t idesc, bool acc) {
#if HAS_TC
    uint32_t en = acc ? 1u : 0u;
    asm volatile(
        "{\n\t.reg .pred p;\n\t"
        "setp.ne.u32 p, %4, 0;\n\t"
        "tcgen05.mma.cta_group::1.kind::f16 [%0], %1, %2, %3, p;\n\t}"
        :: "r"(d_tmem), "l"(a_desc), "l"(b_desc), "r"(idesc), "r"(en) : "memory");
#endif
}
__device__ __forceinline__ void mma_ts(uint32_t d_tmem, uint32_t a_tmem, uint64_t b_desc,
                                       uint32_t idesc, bool acc) {
#if HAS_TC
    uint32_t en = acc ? 1u : 0u;
    asm volatile(
        "{\n\t.reg .pred p;\n\t"
        "setp.ne.u32 p, %4, 0;\n\t"
        "tcgen05.mma.cta_group::1.kind::f16 [%0], [%1], %2, %3, p;\n\t}"
        :: "r"(d_tmem), "r"(a_tmem), "l"(b_desc), "r"(idesc), "r"(en) : "memory");
#endif
}

__device__ __forceinline__ float ex2f(float x) {
    float y;
    asm("ex2.approx.f32 %0, %1;" : "=f"(y) : "f"(x));
    return y;
}
__device__ __forceinline__ uint32_t pack_bf16x2(float a, float b) {
    __nv_bfloat16 h0 = __float2bfloat16(a), h1 = __float2bfloat16(b);
    return ((uint32_t)__bfloat16_as_ushort(h1) << 16) | (uint32_t)__bfloat16_as_ushort(h0);
}
__device__ __forceinline__ void split2(float x, float y, uint32_t& h, uint32_t& l) {
    __nv_bfloat16 hx = __float2bfloat16(x), hy = __float2bfloat16(y);
    h = ((uint32_t)__bfloat16_as_ushort(hy) << 16) | (uint32_t)__bfloat16_as_ushort(hx);
    l = pack_bf16x2(x - __bfloat162float(hx), y - __bfloat162float(hy));
}

// ---------------- Converter: 8 elems/thread, 16B coalesced stores -----------
__device__ __forceinline__ void convert_body8(const float* __restrict__ src,
                                              __nv_bfloat16* __restrict__ hi,
                                              __nv_bfloat16* __restrict__ lo, int mtiles) {
#if HAS_TC
    int idx = blockIdx.x * 256 + threadIdx.x;   // chunk index: m*128 + ck
    int m  = idx >> 7;
    int ck = idx & 127;
    int kc = ck >> 3;
    int r  = m & 127, mt = m >> 7;
    uint32_t off = SWZ128((uint32_t)(r * 128 + (ck & 7) * 16));
    size_t base = ((size_t)(kc * mtiles + mt) << 14) + off;

    const float4* s4 = reinterpret_cast<const float4*>(src + (size_t)m * KDIM + ck * 8);
    float4 a = s4[0], b = s4[1];
    uint4 hq, lq;
    split2(a.x, a.y, hq.x, lq.x);
    split2(a.z, a.w, hq.y, lq.y);
    split2(b.x, b.y, hq.z, lq.z);
    split2(b.z, b.w, hq.w, lq.w);
    *reinterpret_cast<uint4*>(reinterpret_cast<char*>(hi) + base) = hq;
    *reinterpret_cast<uint4*>(reinterpret_cast<char*>(lo) + base) = lq;
#endif
}

__global__ void __launch_bounds__(256)
convert_acts(const float* __restrict__ q, const float* __restrict__ k,
             const float* __restrict__ v) {
#if HAS_TC
    const float* src = (blockIdx.z == 0) ? q : (blockIdx.z == 1) ? k : v;
    size_t off = (blockIdx.z == 0) ? OFF_Q : (blockIdx.z == 1) ? OFF_K : OFF_V;
    convert_body8(src, g_hi + off, g_lo + off, 32);
#endif
}

__global__ void __launch_bounds__(256)
convert_wts(const float* __restrict__ wq, const float* __restrict__ wk,
            const float* __restrict__ wv, const float* __restrict__ wo) {
#if HAS_TC
    const float* src = (blockIdx.z == 0) ? wq : (blockIdx.z == 1) ? wk :
                       (blockIdx.z == 2) ? wv : wo;
    size_t off = (blockIdx.z == 0) ? OFF_WQ : (blockIdx.z == 1) ? OFF_WK :
                 (blockIdx.z == 2) ? OFF_WV : OFF_WO;
    convert_body8(src, g_hi + off, g_lo + off, 8);
#endif
}

// ---------------- tcgen05 split-bf16 GEMM v2: 128x256 tiles ------------------
// Grid (4, 32[, 3]). Per CTA: C[128,256] over K=1024. Two N=128 TMEM halves.
// Stage = A(hi+lo 32KB) + B(hi+lo 64KB, two contiguous 16KB n-tiles each).
#define TILE_B   16384
#define G_STAGES 2
#define G_STAGE_B 98304
#define SM_CTRL  0
#define SM_FULL(s)  (16 + (s) * 8)
#define SM_EMPTY(s) (32 + (s) * 8)
#define SM_DONE  48
#define SM_A_HI(s) (1024 + (s) * G_STAGE_B)
#define SM_A_LO(s) (SM_A_HI(s) + 16384)
#define SM_B_HI(s) (SM_A_HI(s) + 32768)
#define SM_B_LO(s) (SM_A_HI(s) + 65536)
#define GEMM_SMEM (1024 + G_STAGES * G_STAGE_B)   // 197632

__device__ __forceinline__ void
gemm_body(const __nv_bfloat16* __restrict__ ahi, const __nv_bfloat16* __restrict__ alo,
          const __nv_bfloat16* __restrict__ bhi, const __nv_bfloat16* __restrict__ blo,
          float* __restrict__ outflat, int dst, int mtilesA) {
#if HAS_TC
    extern __shared__ char smem[];
    const uint32_t sb = smem_u32(smem);
    const int tid = threadIdx.x, wid = tid >> 5, lid = tid & 31;
    const int mt = blockIdx.y, nt = blockIdx.x;

    if (tid == 0) {
        #pragma unroll
        for (int s = 0; s < G_STAGES; s++) {
            MBARRIER_INIT(sb + SM_FULL(s), 1);
            MBARRIER_INIT(sb + SM_EMPTY(s), 1);
        }
        MBARRIER_INIT(sb + SM_DONE, 1);
        FENCE_PROXY_ASYNC();
    }
    if (wid == 0) TCGEN05_ALLOC(sb + SM_CTRL, 256);
    __syncthreads();

    uint32_t tmem;
    asm volatile("ld.shared.b32 %0, [%1];" : "=r"(tmem) : "r"(sb + SM_CTRL));

    if (tid == 32) {
        int ph[G_STAGES] = {1, 1};
        for (int kc = 0; kc < KC_COUNT; kc++) {
            int s = kc & 1;
            MBARRIER_WAIT_PARITY(sb + SM_EMPTY(s), ph[s]); ph[s] ^= 1;
            MBARRIER_EXPECT_TX(sb + SM_FULL(s), 6 * TILE_B);
            const char* at = (const char*)ahi + ((size_t)(kc * mtilesA + mt) << 14);
            const char* al = (const char*)alo + ((size_t)(kc * mtilesA + mt) << 14);
            const char* bt = (const char*)bhi + ((size_t)(kc * 8 + nt * 2) << 14);
            const char* bl = (const char*)blo + ((size_t)(kc * 8 + nt * 2) << 14);
            BULK_G2S(sb + SM_A_HI(s), at, TILE_B, sb + SM_FULL(s));
            BULK_G2S(sb + SM_A_LO(s), al, TILE_B, sb + SM_FULL(s));
            BULK_G2S(sb + SM_B_HI(s), bt, 2 * TILE_B, sb + SM_FULL(s));
            BULK_G2S(sb + SM_B_LO(s), bl, 2 * TILE_B, sb + SM_FULL(s));
        }
    } else if (tid == 0) {
        for (int kc = 0; kc < KC_COUNT; kc++) {
            int s = kc & 1;
            MBARRIER_WAIT_PARITY(sb + SM_FULL(s), (kc >> 1) & 1);
            uint64_t dah = MAKE_DESC(sb + SM_A_HI(s));
            uint64_t dal = MAKE_DESC(sb + SM_A_LO(s));
            uint64_t dbh = MAKE_DESC(sb + SM_B_HI(s));
            uint64_t dbl = MAKE_DESC(sb + SM_B_LO(s));
            #pragma unroll
            for (int ks = 0; ks < 4; ks++) {
                const bool first = (kc == 0 && ks == 0);
                #pragma unroll
                for (int nh = 0; nh < 2; nh++) {
                    const uint32_t dd = tmem + nh * 128;
                    const uint64_t bo = nh * 1024 + ks * 2;
                    mma_ss(dd, dah + ks * 2, dbh + bo, IDESC_N128, !first);
                    mma_ss(dd, dah + ks * 2, dbl + bo, IDESC_N128, true);
                    mma_ss(dd, dal + ks * 2, dbh + bo, IDESC_N128, true);
                }
            }
            TCGEN05_COMMIT(sb + SM_EMPTY(s));
        }
        TCGEN05_COMMIT(sb + SM_DONE);
    }

    MBARRIER_WAIT_PARITY(sb + SM_DONE, 0);
    TCGEN05_FENCE_AFTER();

    const int m = mt * 128 + (wid & 3) * 32 + lid;
    #pragma unroll
    for (int chunk = 0; chunk < 2; chunk++) {
        const int colbase = (wid >> 2) * 128 + chunk * 64;
        uint32_t d[64];
        TCGEN05_LD_X32(d, tmem + colbase);
        TCGEN05_LD_X32(d + 32, tmem + colbase + 32);
        TCGEN05_WAIT_LD();

        const int ng = nt * 256 + colbase;        // multiple of 64

        if (dst < 3) {
            const int b = m >> 11, sq = m & (SEQ - 1);
            const int h = ng >> 6;
            const int tile = (b * NHEAD + h) * 16 + (sq >> 7);
            const int rr = sq & 127;
            if (dst == 0 || dst == 1) {
                char* hb = (char*)(dst == 0 ? g_tqh : g_tkh) + ((size_t)tile << 14);
                char* lb = (char*)(dst == 0 ? g_tql : g_tkl) + ((size_t)tile << 14);
                #pragma unroll
                for (int c = 0; c < 64; c += 8) {
                    uint4 hq, lq;
                    split2(__uint_as_float(d[c + 0]), __uint_as_float(d[c + 1]), hq.x, lq.x);
                    split2(__uint_as_float(d[c + 2]), __uint_as_float(d[c + 3]), hq.y, lq.y);
                    split2(__uint_as_float(d[c + 4]), __uint_as_float(d[c + 5]), hq.z, lq.z);
                    split2(__uint_as_float(d[c + 6]), __uint_as_float(d[c + 7]), hq.w, lq.w);
                    uint32_t off = SWZ128((uint32_t)(rr * 128 + c * 2));
                    *(uint4*)(hb + off) = hq;
                    *(uint4*)(lb + off) = lq;
                }
            } else {
                char* hb = (char*)g_tvh + ((size_t)tile << 14);
                char* lb = (char*)g_tvl + ((size_t)tile << 14);
                const int kin = rr;
                #pragma unroll
                for (int c = 0; c < 64; c++) {
                    float v0 = __uint_as_float(d[c]);
                    __nv_bfloat16 h0 = __float2bfloat16(v0);
                    __nv_bfloat16 l0 = __float2bfloat16(v0 - __bfloat162float(h0));
                    uint32_t bo = (uint32_t)(((c >> 3) + (kin >> 6) * 8) * 1024 +
                                             (c & 7) * 128 + (kin & 63) * 2);
                    uint32_t off = SWZ128(bo);
                    *(__nv_bfloat16*)(hb + off) = h0;
                    *(__nv_bfloat16*)(lb + off) = l0;
                }
            }
        } else {
            float* row = outflat + (size_t)m * DMODEL + ng;
            #pragma unroll
            for (int c = 0; c < 64; c += 4) {
                float4 v = make_float4(__uint_as_float(d[c]), __uint_as_float(d[c + 1]),
                                       __uint_as_float(d[c + 2]), __uint_as_float(d[c + 3]));
                *reinterpret_cast<float4*>(row + c) = v;
            }
        }
    }
    TCGEN05_FENCE_BEFORE();

    __syncthreads();
    if (wid == 0) {
        TCGEN05_RELINQ();
        TCGEN05_DEALLOC(tmem, 256);
    }
#endif
}

__global__ void __launch_bounds__(256) gemm_qkv() {
#if HAS_TC
    const int z = blockIdx.z;
    const size_t aoff = (z == 0) ? OFF_Q : (z == 1) ? OFF_K : OFF_V;
    const size_t boff = (z == 0) ? OFF_WQ : (z == 1) ? OFF_WK : OFF_WV;
    gemm_body(g_hi + aoff, g_lo + aoff, g_hi + boff, g_lo + boff, nullptr, z, 32);
#endif
}

__global__ void __launch_bounds__(256) gemm_wo(float* __restrict__ out) {
#if HAS_TC
    gemm_body(g_hi + OFF_CTX, g_lo + OFF_CTX, g_hi + OFF_WO, g_lo + OFF_WO, out, 3, 32);
#endif
}

// ---------------- tcgen05 flash attention (R7 version, proven 364.6us) ------
#define F_TM     0
#define F_FULL(u) (16 + (u) * 8)   // 3 TMA stages
#define F_SD(b)   (40 + (b) * 8)   // MMA1 done, per S buffer
#define F_OD(b)   (56 + (b) * 8)   // MMA2 done, per parity
#define F_QFULL  72
#define F_LRED   512               // 256 floats
#define F_QH     2048
#define F_QL     (F_QH + 16384)
#define F_STG    (F_QL + 16384)
#define F_STGSZ  65536
#define FLASH_SMEM (F_STG + 3 * F_STGSZ)   // 231424
#define TC_S0  0
#define TC_S1  128
#define TC_O   256
#define TC_PH  320
#define TC_PL  384

__global__ void __launch_bounds__(256)
flash_tc(const int* __restrict__ mask) {
#if HAS_TC
    extern __shared__ char fsm[];
    const uint32_t sb = smem_u32(fsm);
    const int tid = threadIdx.x;
    const int lane = tid & 31;
    const int sp = (tid >> 5) & 3;
    const int ch = tid >> 7;              // column half
    const int r = sp * 32 + lane;         // row 0..127
    const int bh = blockIdx.z * NHEAD + blockIdx.y;
    const int qt = blockIdx.x;

    if (tid == 0) {
        MBARRIER_INIT(sb + F_FULL(0), 1);
        MBARRIER_INIT(sb + F_FULL(1), 1);
        MBARRIER_INIT(sb + F_FULL(2), 1);
        MBARRIER_INIT(sb + F_SD(0), 1);
        MBARRIER_INIT(sb + F_SD(1), 1);
        MBARRIER_INIT(sb + F_OD(0), 1);
        MBARRIER_INIT(sb + F_OD(1), 1);
        MBARRIER_INIT(sb + F_QFULL, 1);
        FENCE_PROXY_ASYNC();
    }
    if ((tid >> 5) == 0) TCGEN05_ALLOC(sb + F_TM, 512);
    __syncthreads();

    uint32_t tmem;
    asm volatile("ld.shared.b32 %0, [%1];" : "=r"(tmem) : "r"(sb + F_TM));

    auto issue_stage = [&](int tile, int u) {
        const size_t koff = ((size_t)(bh * 16 + tile)) << 14;
        const uint32_t d1 = sb + F_STG + u * F_STGSZ;
        MBARRIER_EXPECT_TX(sb + F_FULL(u), 4 * TILE_B);
        BULK_G2S(d1 + 0,     (const char*)g_tkh + koff, TILE_B, sb + F_FULL(u));
        BULK_G2S(d1 + 16384, (const char*)g_tkl + koff, TILE_B, sb + F_FULL(u));
        BULK_G2S(d1 + 32768, (const char*)g_tvh + koff, TILE_B, sb + F_FULL(u));
        BULK_G2S(d1 + 49152, (const char*)g_tvl + koff, TILE_B, sb + F_FULL(u));
    };
    auto do_mma1 = [&](uint32_t stg, uint32_t sdst) {
        const uint64_t dqh = MAKE_DESC(sb + F_QH);
        const uint64_t dql = MAKE_DESC(sb + F_QL);
        const uint64_t dkh = MAKE_DESC(stg);
        const uint64_t dkl = MAKE_DESC(stg + 16384);
        #pragma unroll
        for (int ks = 0; ks < 4; ks++)
            mma_ss(sdst, dqh + ks * 2, dkh + ks * 2, IDESC_N128, ks > 0);
        #pragma unroll
        for (int ks = 0; ks < 4; ks++)
            mma_ss(sdst, dqh + ks * 2, dkl + ks * 2, IDESC_N128, true);
        #pragma unroll
        for (int ks = 0; ks < 4; ks++)
            mma_ss(sdst, dql + ks * 2, dkh + ks * 2, IDESC_N128, true);
    };
    auto do_mma2 = [&](uint32_t stg, bool first) {
        const uint64_t dvh = MAKE_DESC(stg + 32768);
        const uint64_t dvl = MAKE_DESC(stg + 49152);
        const int voff[8] = {0, 2, 4, 6, 512, 514, 516, 518};
        #pragma unroll
        for (int ks = 0; ks < 8; ks++)
            mma_ts(tmem + TC_O, tmem + TC_PH + ks * 8, dvh + voff[ks], IDESC_N64,
                   !(first && ks == 0));
        #pragma unroll
        for (int ks = 0; ks < 8; ks++)
            mma_ts(tmem + TC_O, tmem + TC_PH + ks * 8, dvl + voff[ks], IDESC_N64, true);
        #pragma unroll
        for (int ks = 0; ks < 8; ks++)
            mma_ts(tmem + TC_O, tmem + TC_PL + ks * 8, dvh + voff[ks], IDESC_N64, true);
    };

    int fp[3] = {0, 0, 0};
    if (tid == 0) {
        const size_t qoff = ((size_t)(bh * 16 + qt)) << 14;
        MBARRIER_EXPECT_TX(sb + F_QFULL, 32768);
        BULK_G2S(sb + F_QH, (const char*)g_tqh + qoff, TILE_B, sb + F_QFULL);
        BULK_G2S(sb + F_QL, (const char*)g_tql + qoff, TILE_B, sb + F_QFULL);
        issue_stage(0, 0);
        issue_stage(1, 1);
        issue_stage(2, 2);
        MBARRIER_WAIT_PARITY(sb + F_QFULL, 0);
        MBARRIER_WAIT_PARITY(sb + F_FULL(0), 0); fp[0] = 1;
        do_mma1(sb + F_STG, tmem + TC_S0);
        TCGEN05_COMMIT(sb + F_SD(0));
    }

    const float cs = 0.125f * 1.4426950408889634f;
    const float CB = 20.0f;
    const int* mk = mask + blockIdx.z * SEQ;
    int sdp[2] = {0, 0};
    float lsum = 0.f;

    for (int j = 0; j < 16; j++) {
        const int b = j & 1;
        if (tid == 0) {
            if (j >= 1 && j + 2 <= 15) {
                MBARRIER_WAIT_PARITY(sb + F_OD((j - 1) & 1), ((j - 1) >> 1) & 1);
                issue_stage(j + 2, (j + 2) % 3);
            }
            if (j + 1 <= 15) {
                const int u = (j + 1) % 3;
                MBARRIER_WAIT_PARITY(sb + F_FULL(u), fp[u]); fp[u] ^= 1;
                do_mma1(sb + F_STG + u * F_STGSZ, tmem + (b ? TC_S0 : TC_S1));
                TCGEN05_COMMIT(sb + F_SD(b ^ 1));
            }
        }

        MBARRIER_WAIT_PARITY(sb + F_SD(b), sdp[b]); sdp[b] ^= 1;
        TCGEN05_FENCE_AFTER();

        const uint32_t sbase = tmem + (b ? TC_S1 : TC_S0) + ch * 64;
        const int* mrow = mk + j * 128 + ch * 64;

        #pragma unroll
        for (int half = 0; half < 2; half++) {
            uint32_t sr[32];
            TCGEN05_LD_X32(sr, sbase + half * 32);
            TCGEN05_WAIT_LD();

            uint32_t ph[16], pl[16];
            const int* m2 = mrow + half * 32;
            #pragma unroll
            for (int g = 0; g < 8; g++) {
                int4 mm = *reinterpret_cast<const int4*>(m2 + 4 * g);
                float p0 = mm.x ? ex2f(fmaf(__uint_as_float(sr[4 * g + 0]), cs, -CB)) : 0.f;
                float p1 = mm.y ? ex2f(fmaf(__uint_as_float(sr[4 * g + 1]), cs, -CB)) : 0.f;
                float p2 = mm.z ? ex2f(fmaf(__uint_as_float(sr[4 * g + 2]), cs, -CB)) : 0.f;
                float p3 = mm.w ? ex2f(fmaf(__uint_as_float(sr[4 * g + 3]), cs, -CB)) : 0.f;
                lsum += (p0 + p1) + (p2 + p3);
                split2(p0, p1, ph[2 * g],     pl[2 * g]);
                split2(p2, p3, ph[2 * g + 1], pl[2 * g + 1]);
            }

            if (half == 0 && j >= 1) {
                MBARRIER_WAIT_PARITY(sb + F_OD((j - 1) & 1), ((j - 1) >> 1) & 1);
                TCGEN05_FENCE_AFTER();
            }
            TCGEN05_ST_X16(tmem + TC_PH + ch * 32 + half * 16, ph);
            TCGEN05_ST_X16(tmem + TC_PL + ch * 32 + half * 16, pl);
        }
        TCGEN05_WAIT_ST();
        TCGEN05_FENCE_BEFORE();
        __syncthreads();

        if (tid == 0) {
            TCGEN05_FENCE_AFTER();
            do_mma2(sb + F_STG + (j % 3) * F_STGSZ, j == 0);
            TCGEN05_COMMIT(sb + F_OD(b));
        }
    }

    MBARRIER_WAIT_PARITY(sb + F_OD(1), 1);
    TCGEN05_FENCE_AFTER();
    uint32_t od[32];
    TCGEN05_LD_X32(od, tmem + TC_O + ch * 32);
    TCGEN05_WAIT_LD();
    TCGEN05_FENCE_BEFORE();

    float* lred = (float*)(fsm + F_LRED);
    lred[ch * 128 + r] = lsum;
    __syncthreads();
    const float ltot = lsum + lred[(1 - ch) * 128 + r];
    const float inv = 1.f / ltot;

    const int h = blockIdx.y;
    const int mt_g = blockIdx.z * 16 + qt;
    char* hb = (char*)g_hi + (((size_t)OFF_CTX) << 1) + (((size_t)(h * 32 + mt_g)) << 14);
    char* lb = (char*)g_lo + (((size_t)OFF_CTX) << 1) + (((size_t)(h * 32 + mt_g)) << 14);
    #pragma unroll
    for (int c = 0; c < 32; c += 8) {
        uint4 hq, lq;
        split2(__uint_as_float(od[c + 0]) * inv, __uint_as_float(od[c + 1]) * inv, hq.x, lq.x);
        split2(__uint_as_float(od[c + 2]) * inv, __uint_as_float(od[c + 3]) * inv, hq.y, lq.y);
        split2(__uint_as_float(od[c + 4]) * inv, __uint_as_float(od[c + 5]) * inv, hq.z, lq.z);
        split2(__uint_as_float(od[c + 6]) * inv, __uint_as_float(od[c + 7]) * inv, hq.w, lq.w);
        uint32_t off = SWZ128((uint32_t)(r * 128 + (ch * 32 + c) * 2));
        *(uint4*)(hb + off) = hq;
        *(uint4*)(lb + off) = lq;
    }

    __syncthreads();
    if ((tid >> 5) == 0) {
        TCGEN05_RELINQ();
        TCGEN05_DEALLOC(tmem, 512);
    }
#endif
}

// ---------------- Launch -----------------------------------------------------
extern "C" void kernel_launch(void* const* d_in, const int* in_sizes, int n_in,
                              void* d_out, int out_size) {
    const float* q    = (const float*)d_in[0];
    const float* k    = (const float*)d_in[1];
    const float* v    = (const float*)d_in[2];
    const int*   mask = (const int*)  d_in[3];
    const float* Wq   = (const float*)d_in[4];
    const float* Wk   = (const float*)d_in[5];
    const float* Wv   = (const float*)d_in[6];
    const float* Wo   = (const float*)d_in[7];
    float* out = (float*)d_out;

    cudaFuncSetAttribute(gemm_qkv, cudaFuncAttributeMaxDynamicSharedMemorySize, GEMM_SMEM);
    cudaFuncSetAttribute(gemm_wo, cudaFuncAttributeMaxDynamicSharedMemorySize, GEMM_SMEM);
    cudaFuncSetAttribute(flash_tc, cudaFuncAttributeMaxDynamicSharedMemorySize, FLASH_SMEM);

    dim3 qkv_grid(4, 32, 3);                 // 128x256 tiles, 3 GEMMs merged
    dim3 wo_grid(4, 32);
    dim3 fa_grid_tc(SEQ / 128, NHEAD, BATCH);

    convert_acts<<<dim3(2048, 1, 3), 256>>>(q, k, v);
    convert_wts<<<dim3(512, 1, 4), 256>>>(Wq, Wk, Wv, Wo);

    gemm_qkv<<<qkv_grid, 256, GEMM_SMEM>>>();

    flash_tc<<<fa_grid_tc, 256, FLASH_SMEM>>>(mask);

    gemm_wo<<<wo_grid, 256, GEMM_SMEM>>>(out);
}